// round 1
// baseline (speedup 1.0000x reference)
#include <cuda_runtime.h>
#include <cstdint>

#define B_N   65536
#define IN_N  512
#define H_N   1024
#define STEPS 10
#define BETA  0.9f
#define THR   1.0f

// ---------------- static scratch (module-load allocated, no runtime alloc) ----------------
__device__ float    g_cur1[(size_t)B_N * H_N];          // 268 MB: x@W1+b1
__device__ unsigned g_s1bits[STEPS][H_N / 32][B_N];     // 84 MB: layer-1 spike bitplanes
__device__ float    g_cur2[(size_t)B_N * H_N];          // 268 MB: one step of s1@W2
__device__ float    g_m2[(size_t)B_N * H_N];            // 268 MB: layer-2 membrane state
__device__ float    g_mo[B_N];
__device__ float    g_acc[B_N];

// ---------------- K1: cur1 = x @ W1 + b1   (fp32 SIMT, 128x128x16 tiles) ----------------
__global__ __launch_bounds__(256) void k1_gemm(const float* __restrict__ X,
                                               const float* __restrict__ W1,
                                               const float* __restrict__ b1) {
    __shared__ float As[16][128];
    __shared__ float Bs[16][128];
    const int tid = threadIdx.x;
    const int tx = tid & 15, ty = tid >> 4;
    const int m0 = blockIdx.y * 128;
    const int n0 = blockIdx.x * 128;

    float acc[8][8];
#pragma unroll
    for (int i = 0; i < 8; i++)
#pragma unroll
        for (int j = 0; j < 8; j++) acc[i][j] = 0.f;

    for (int kc = 0; kc < IN_N; kc += 16) {
        float4 av[2], bv[2];
#pragma unroll
        for (int l = 0; l < 2; l++) {
            int f = tid + l * 256;            // 0..511
            int row = f >> 2, kq = (f & 3) * 4;
            av[l] = *(const float4*)&X[(size_t)(m0 + row) * IN_N + kc + kq];
            int kr = f >> 5, c4 = (f & 31) * 4;
            bv[l] = *(const float4*)&W1[(size_t)(kc + kr) * H_N + n0 + c4];
        }
        __syncthreads();
#pragma unroll
        for (int l = 0; l < 2; l++) {
            int f = tid + l * 256;
            int row = f >> 2, kq = (f & 3) * 4;
            As[kq + 0][row] = av[l].x; As[kq + 1][row] = av[l].y;
            As[kq + 2][row] = av[l].z; As[kq + 3][row] = av[l].w;
            int kr = f >> 5, c4 = (f & 31) * 4;
            *(float4*)&Bs[kr][c4] = bv[l];
        }
        __syncthreads();
#pragma unroll
        for (int kk = 0; kk < 16; kk++) {
            float a[8], bb[8];
            *(float4*)&a[0]  = *(float4*)&As[kk][ty * 8];
            *(float4*)&a[4]  = *(float4*)&As[kk][ty * 8 + 4];
            *(float4*)&bb[0] = *(float4*)&Bs[kk][tx * 8];
            *(float4*)&bb[4] = *(float4*)&Bs[kk][tx * 8 + 4];
#pragma unroll
            for (int i = 0; i < 8; i++)
#pragma unroll
                for (int j = 0; j < 8; j++) acc[i][j] += a[i] * bb[j];
        }
    }

    float bias[8];
#pragma unroll
    for (int j = 0; j < 8; j++) bias[j] = b1[n0 + tx * 8 + j];
#pragma unroll
    for (int i = 0; i < 8; i++) {
        int row = m0 + ty * 8 + i;
        float4 o0, o1;
        o0.x = acc[i][0] + bias[0]; o0.y = acc[i][1] + bias[1];
        o0.z = acc[i][2] + bias[2]; o0.w = acc[i][3] + bias[3];
        o1.x = acc[i][4] + bias[4]; o1.y = acc[i][5] + bias[5];
        o1.z = acc[i][6] + bias[6]; o1.w = acc[i][7] + bias[7];
        *(float4*)&g_cur1[(size_t)row * H_N + n0 + tx * 8]     = o0;
        *(float4*)&g_cur1[(size_t)row * H_N + n0 + tx * 8 + 4] = o1;
    }
}

// ---------------- K2: layer-1 LIF recurrence -> packed spike bitplanes ----------------
// warp W handles (b = W & 65535, j = W >> 16); lane = neuron h' = j*32+lane
__global__ __launch_bounds__(256) void k2_s1gen() {
    const int W    = blockIdx.x * 8 + (threadIdx.x >> 5);
    const int lane = threadIdx.x & 31;
    const int b = W & (B_N - 1);
    const int j = W >> 16;
    const float c = g_cur1[(size_t)b * H_N + j * 32 + lane];
    float m = 0.f;
#pragma unroll
    for (int t = 0; t < STEPS; t++) {
        float r = (m > THR) ? THR : 0.f;   // reset from PREVIOUS membrane
        m = BETA * m + c - r;
        unsigned bal = __ballot_sync(0xFFFFFFFFu, m > THR);
        if (lane == 0) g_s1bits[t][j][b] = bal;
    }
}

// ---------------- K3: cur2_t = s1_t @ W2  (binary-sparse, exact fp32) ----------------
// CTA: 512 thr = 16 warps; warp w owns rows rbase..rbase+15, cols n0+lane*4..+3.
// W2 staged in smem 32 k-rows at a time; warp-uniform ffs bit-scan over spike mask.
__global__ __launch_bounds__(512) void k3_spmm(int t, const float* __restrict__ W2) {
    __shared__ float4 sW[32][32];          // [k within chunk][col/4]
    const int tid   = threadIdx.x;
    const int lane  = tid & 31;
    const int wid   = tid >> 5;            // 0..15
    const int n0    = blockIdx.x * 128;
    const int rbase = blockIdx.y * 256 + wid * 16;

    float4 acc[16];
#pragma unroll
    for (int r = 0; r < 16; r++) acc[r] = make_float4(0.f, 0.f, 0.f, 0.f);

    for (int kc = 0; kc < H_N / 32; kc++) {
        __syncthreads();
#pragma unroll
        for (int l = 0; l < 2; l++) {
            int f = tid + l * 512;         // 0..1023
            int kr = f >> 5, c4 = f & 31;
            sW[kr][c4] = *(const float4*)&W2[(size_t)(kc * 32 + kr) * H_N + n0 + c4 * 4];
        }
        __syncthreads();

        unsigned mw = 0;
        if (lane < 16) mw = g_s1bits[t][kc][rbase + lane];
#pragma unroll
        for (int r = 0; r < 16; r++) {
            unsigned w = __shfl_sync(0xFFFFFFFFu, mw, r);
            while (w) {
                int bit = __ffs(w) - 1;
                w &= w - 1;
                float4 v = sW[bit][lane];
                acc[r].x += v.x; acc[r].y += v.y; acc[r].z += v.z; acc[r].w += v.w;
            }
        }
    }
#pragma unroll
    for (int r = 0; r < 16; r++)
        *(float4*)&g_cur2[(size_t)(rbase + r) * H_N + n0 + lane * 4] = acc[r];
}

// ---------------- K4: layer-2 LIF + s2@Wo + output LIF (one step) ----------------
__global__ __launch_bounds__(256) void k4_step(int t, const float* __restrict__ Wo,
                                               const float* __restrict__ b2,
                                               const float* __restrict__ bo,
                                               float* __restrict__ out) {
    __shared__ float red[8];
    const int b   = blockIdx.x;
    const int tid = threadIdx.x;
    const size_t base = (size_t)b * H_N + tid * 4;

    float4 c  = *(const float4*)&g_cur2[base];
    float4 bv = *(const float4*)&b2[tid * 4];
    c.x += bv.x; c.y += bv.y; c.z += bv.z; c.w += bv.w;

    float4 m = make_float4(0.f, 0.f, 0.f, 0.f);
    if (t) m = *(const float4*)&g_m2[base];
    float4 wo = *(const float4*)&Wo[tid * 4];

    float p = 0.f;
    float r;
    r = (m.x > THR) ? THR : 0.f; m.x = BETA * m.x + c.x - r; if (m.x > THR) p += wo.x;
    r = (m.y > THR) ? THR : 0.f; m.y = BETA * m.y + c.y - r; if (m.y > THR) p += wo.y;
    r = (m.z > THR) ? THR : 0.f; m.z = BETA * m.z + c.z - r; if (m.z > THR) p += wo.z;
    r = (m.w > THR) ? THR : 0.f; m.w = BETA * m.w + c.w - r; if (m.w > THR) p += wo.w;

    if (t != STEPS - 1) *(float4*)&g_m2[base] = m;

#pragma unroll
    for (int o = 16; o; o >>= 1) p += __shfl_down_sync(0xFFFFFFFFu, p, o);
    if ((tid & 31) == 0) red[tid >> 5] = p;
    __syncthreads();
    if (tid == 0) {
        float total = bo[0];
#pragma unroll
        for (int wgi = 0; wgi < 8; wgi++) total += red[wgi];
        float mo = 0.f, a = 0.f;
        if (t) { mo = g_mo[b]; a = g_acc[b]; }
        float ro = (mo > THR) ? THR : 0.f;
        mo = BETA * mo + total - ro;
        a += mo;
        if (t == STEPS - 1) out[b] = a * (1.f / STEPS);
        else { g_mo[b] = mo; g_acc[b] = a; }
    }
}

// ---------------- launcher ----------------
extern "C" void kernel_launch(void* const* d_in, const int* in_sizes, int n_in,
                              void* d_out, int out_size) {
    const float* x  = (const float*)d_in[0];
    const float* W1 = (const float*)d_in[1];
    const float* b1 = (const float*)d_in[2];
    const float* W2 = (const float*)d_in[3];
    const float* b2 = (const float*)d_in[4];
    const float* Wo = (const float*)d_in[5];
    const float* bo = (const float*)d_in[6];
    float* out = (float*)d_out;

    k1_gemm<<<dim3(H_N / 128, B_N / 128), 256>>>(x, W1, b1);
    k2_s1gen<<<(B_N / 8) * (H_N / 32), 256>>>();
    for (int t = 0; t < STEPS; t++) {
        k3_spmm<<<dim3(H_N / 128, B_N / 256), 512>>>(t, W2);
        k4_step<<<B_N, 256>>>(t, Wo, b2, bo, out);
    }
}